// round 7
// baseline (speedup 1.0000x reference)
#include <cuda_runtime.h>
#include <cuda_bf16.h>
#include <cstdint>

// Problem constants
#define BATCH      32768
#define INPUT_DIM  256
#define NNEUR      128
#define NDEG       8                     // D+1 coefficients per input dim
#define NFEAT      (INPUT_DIM * NDEG)    // 2048
#define NG2        (BATCH / 2)           // 16384 groups of 2 rows

#define GRID_MAIN  512                   // 512 blocks x 8 warps x 4 groups = 16384
#define THREADS    256
#define NWARPS     (GRID_MAIN * THREADS / 32)   // 4096
#define GROUPS_PER_WARP (NG2 / NWARPS)          // 4

// Transformed + packed coefficient table (8 KB), produced by kan_prep.
// Granule linear index m in [0,512): m = (q*4 + gj)*32 + lane.
// Lane owns inputs i = lane*8 .. lane*8+7 (pairs p = lane*4+q).
// Granule gj of pair p holds coefficients (c_{2gj}, c_{2gj+1}) for both
// inputs of the pair: [ c_{2gj}(i0), c_{2gj}(i1), c_{2gj+1}(i0), c_{2gj+1}(i1) ].
// Coefficient order c_0..c_7 = e0,e1,e2,e3,o0,o1,o2,o3 (even/odd Horner).
__device__ float g_pack[NFEAT];

// ---------------------------------------------------------------------------
// packed f32x2 helpers (sm_103a FFMA2 path — only reachable via PTX)
// ---------------------------------------------------------------------------
__device__ __forceinline__ float2 ffma2(float2 a, float2 b, float2 c) {
    float2 d;
    asm("fma.rn.f32x2 %0, %1, %2, %3;"
        : "=l"(reinterpret_cast<unsigned long long&>(d))
        : "l"(reinterpret_cast<unsigned long long&>(a)),
          "l"(reinterpret_cast<unsigned long long&>(b)),
          "l"(reinterpret_cast<unsigned long long&>(c)));
    return d;
}
__device__ __forceinline__ float2 fmul2(float2 a, float2 b) {
    float2 d;
    asm("mul.rn.f32x2 %0, %1, %2;"
        : "=l"(reinterpret_cast<unsigned long long&>(d))
        : "l"(reinterpret_cast<unsigned long long&>(a)),
          "l"(reinterpret_cast<unsigned long long&>(b)));
    return d;
}
__device__ __forceinline__ float2 fadd2(float2 a, float2 b) {
    float2 d;
    asm("add.rn.f32x2 %0, %1, %2;"
        : "=l"(reinterpret_cast<unsigned long long&>(d))
        : "l"(reinterpret_cast<unsigned long long&>(a)),
          "l"(reinterpret_cast<unsigned long long&>(b)));
    return d;
}

// ---------------------------------------------------------------------------
// Prep kernel: C[f] = sum_n coeffs[n][f]; convert Chebyshev T_0..T_7 coeffs
// per input to even/odd y-Horner (y = x^2) coeffs; scatter into g_pack.
// grid = 64 blocks x 256 threads; block handles 32 features = 4 inputs.
// ---------------------------------------------------------------------------
__global__ void kan_prep(const float* __restrict__ coeffs) {
    __shared__ float sh[8][32];
    __shared__ float cs[32];
    const int t  = threadIdx.x;
    const int fl = t & 31;
    const int g  = t >> 5;
    const int f  = blockIdx.x * 32 + fl;

    float s = 0.0f;
#pragma unroll
    for (int n = 0; n < 16; n++)
        s += coeffs[(g * 16 + n) * NFEAT + f];
    sh[g][fl] = s;
    __syncthreads();

    if (t < 32) {
        float c = 0.0f;
#pragma unroll
        for (int gg = 0; gg < 8; gg++) c += sh[gg][t];
        cs[t] = c;
    }
    __syncthreads();

    if (t < 4) {
        const int i = blockIdx.x * 4 + t;
        float C[8];
#pragma unroll
        for (int d = 0; d < 8; d++) C[d] = cs[t * 8 + d];

        // T0=1; T1=x; T2=2y-1; T3=x(4y-3); T4=8y^2-8y+1; T5=x(16y^2-20y+5)
        // T6=32y^3-48y^2+18y-1; T7=x(64y^3-112y^2+56y-7)   (y = x^2)
        float cf[8];
        cf[0] = C[0] - C[2] + C[4] - C[6];               // e0
        cf[1] = 2.f*C[2] - 8.f*C[4] + 18.f*C[6];         // e1
        cf[2] = 8.f*C[4] - 48.f*C[6];                    // e2
        cf[3] = 32.f*C[6];                               // e3
        cf[4] = C[1] - 3.f*C[3] + 5.f*C[5] - 7.f*C[7];   // o0
        cf[5] = 4.f*C[3] - 20.f*C[5] + 56.f*C[7];        // o1
        cf[6] = 16.f*C[5] - 112.f*C[7];                  // o2
        cf[7] = 64.f*C[7];                               // o3

        const int p    = i >> 1;
        const int lane = p >> 2;
        const int q    = p & 3;
        const int e    = i & 1;
#pragma unroll
        for (int j = 0; j < 8; j++) {
            const int gj = j >> 1;
            g_pack[((q * 4 + gj) * 32 + lane) * 4 + (j & 1) * 2 + e] = cf[j];
        }
    }
}

// ---------------------------------------------------------------------------
// Main kernel: HIGH OCCUPANCY. Coefficients live in SHARED MEMORY (8 KB per
// block, read as 4 conflict-free LDS.128 per q-step, reused for both rows),
// freeing ~64 registers -> <=64 regs/thread -> 4 blocks/SM -> 32 warps/SM.
// 512 blocks x 8 warps, each warp handles exactly 4 groups of 2 rows.
// Plain LDG for x; 8 warps/SMSP hide the DRAM latency.
// ---------------------------------------------------------------------------
__global__ __launch_bounds__(THREADS, 4)
void kan_main(const float* __restrict__ x, float* __restrict__ out) {
    __shared__ float4 sv[512];   // 8 KB coefficient table

    const int tid  = threadIdx.x;
    const int lane = tid & 31;
    const int w    = tid >> 5;

    // Cooperative copy of the coefficient table into smem (2 float4/thread).
    const float4* __restrict__ gp4 = reinterpret_cast<const float4*>(g_pack);
    sv[tid]       = gp4[tid];
    sv[tid + 256] = gp4[tid + 256];
    __syncthreads();

    const float4* __restrict__ xr = reinterpret_cast<const float4*>(x);
    const int warpId = blockIdx.x * (THREADS / 32) + w;

#pragma unroll
    for (int k = 0; k < GROUPS_PER_WARP; k++) {
        const int grp  = warpId + k * NWARPS;
        const int base = grp * (2 * INPUT_DIM / 4) + lane * 2;

        // 4 independent LDG.128: 2 rows x 32 B per lane.
        const float4 x0 = xr[base];
        const float4 x1 = xr[base + 1];
        const float4 x2 = xr[base + 64];
        const float4 x3 = xr[base + 65];

        float2 acc0 = make_float2(0.f, 0.f);
        float2 acc1 = make_float2(0.f, 0.f);

#pragma unroll
        for (int q = 0; q < 4; q++) {
            // Coefficients for this q-step: 4 conflict-free LDS.128,
            // shared by both rows.
            const float4 g0 = sv[q * 128 +       lane];   // (e0, e1)
            const float4 g1 = sv[q * 128 +  32 + lane];   // (e2, e3)
            const float4 g2 = sv[q * 128 +  64 + lane];   // (o0, o1)
            const float4 g3 = sv[q * 128 +  96 + lane];   // (o2, o3)
            const float2 e0 = make_float2(g0.x, g0.y), e1 = make_float2(g0.z, g0.w);
            const float2 e2 = make_float2(g1.x, g1.y), e3 = make_float2(g1.z, g1.w);
            const float2 o0 = make_float2(g2.x, g2.y), o1 = make_float2(g2.z, g2.w);
            const float2 o2 = make_float2(g3.x, g3.y), o3 = make_float2(g3.z, g3.w);

            // Row 0 input pair q.
            float2 X = (q < 2) ? ((q & 1) ? make_float2(x0.z, x0.w) : make_float2(x0.x, x0.y))
                               : ((q & 1) ? make_float2(x1.z, x1.w) : make_float2(x1.x, x1.y));
            float2 Y = fmul2(X, X);
            float2 ev = ffma2(e3, Y, e2);
            ev = ffma2(ev, Y, e1);
            ev = ffma2(ev, Y, e0);
            float2 od = ffma2(o3, Y, o2);
            od = ffma2(od, Y, o1);
            od = ffma2(od, Y, o0);
            acc0 = fadd2(acc0, ev);
            acc0 = ffma2(od, X, acc0);

            // Row 1 input pair q.
            X = (q < 2) ? ((q & 1) ? make_float2(x2.z, x2.w) : make_float2(x2.x, x2.y))
                        : ((q & 1) ? make_float2(x3.z, x3.w) : make_float2(x3.x, x3.y));
            Y = fmul2(X, X);
            ev = ffma2(e3, Y, e2);
            ev = ffma2(ev, Y, e1);
            ev = ffma2(ev, Y, e0);
            od = ffma2(o3, Y, o2);
            od = ffma2(od, Y, o1);
            od = ffma2(od, Y, o0);
            acc1 = fadd2(acc1, ev);
            acc1 = ffma2(od, X, acc1);
        }

        // Shared-butterfly reduction for both rows: 9 shuffles total.
        float s0 = acc0.x + acc0.y;
        float s1 = acc1.x + acc1.y;
#pragma unroll
        for (int off = 16; off >= 2; off >>= 1) {
            s0 += __shfl_xor_sync(0xffffffffu, s0, off);
            s1 += __shfl_xor_sync(0xffffffffu, s1, off);
        }
        float u = (lane & 2) ? s1 : s0;
        u += __shfl_xor_sync(0xffffffffu, u, 1);
        if (lane == 0)      out[grp * 2]     = u;
        else if (lane == 2) out[grp * 2 + 1] = u;
    }
}

// ---------------------------------------------------------------------------
extern "C" void kernel_launch(void* const* d_in, const int* in_sizes, int n_in,
                              void* d_out, int out_size) {
    const float* x      = (const float*)d_in[0];   // [32768, 256]
    const float* coeffs = (const float*)d_in[1];   // [128, 2048]
    float* out          = (float*)d_out;           // [32768, 1]
    (void)in_sizes; (void)n_in; (void)out_size;

    kan_prep<<<NFEAT / 32, 256>>>(coeffs);
    kan_main<<<GRID_MAIN, THREADS>>>(x, out);
}

// round 8
// speedup vs baseline: 1.5389x; 1.5389x over previous
#include <cuda_runtime.h>
#include <cuda_bf16.h>
#include <cstdint>

// Problem constants
#define BATCH      32768
#define INPUT_DIM  256
#define NNEUR      128
#define NDEG       8                     // D+1 coefficients per input dim
#define NFEAT      (INPUT_DIM * NDEG)    // 2048
#define NG4        (BATCH / 4)           // 8192 groups of 4 rows

#define GRID_MAIN  304                   // 152 SMs x 2 resident blocks
#define THREADS    256
#define NWARPS     (GRID_MAIN * THREADS / 32)   // 2432

// Transformed + packed coefficient table (8 KB), produced by kan_prep.
// Granule linear index m in [0,512): m = (q*4 + gj)*32 + lane.
// Lane owns inputs i = lane*8 .. lane*8+7 (pairs p = lane*4+q).
// Granule gj of pair p holds coefficients (c_{2gj}, c_{2gj+1}) for both
// inputs of the pair: [ c_{2gj}(i0), c_{2gj}(i1), c_{2gj+1}(i0), c_{2gj+1}(i1) ].
// Coefficient order c_0..c_7 = e0,e1,e2,e3,o0,o1,o2,o3 (even/odd Horner).
__device__ float g_pack[NFEAT];
// Per-prep-block partial sums of e0 (prep block b covers inputs 2b, 2b+1).
// Lane's e0 constant = sum of g_e0h[4*lane .. 4*lane+3].
__device__ float g_e0h[128];

// ---------------------------------------------------------------------------
// packed f32x2 helpers (sm_103a FFMA2 path — only reachable via PTX)
// ---------------------------------------------------------------------------
__device__ __forceinline__ float2 ffma2(float2 a, float2 b, float2 c) {
    float2 d;
    asm("fma.rn.f32x2 %0, %1, %2, %3;"
        : "=l"(reinterpret_cast<unsigned long long&>(d))
        : "l"(reinterpret_cast<unsigned long long&>(a)),
          "l"(reinterpret_cast<unsigned long long&>(b)),
          "l"(reinterpret_cast<unsigned long long&>(c)));
    return d;
}
__device__ __forceinline__ float2 fmul2(float2 a, float2 b) {
    float2 d;
    asm("mul.rn.f32x2 %0, %1, %2;"
        : "=l"(reinterpret_cast<unsigned long long&>(d))
        : "l"(reinterpret_cast<unsigned long long&>(a)),
          "l"(reinterpret_cast<unsigned long long&>(b)));
    return d;
}

// ---------------------------------------------------------------------------
// Prep kernel (fast 128-block variant from round 2, + e0 partials + PDL
// early trigger). C[f] = sum_n coeffs[n][f]; convert Chebyshev T_0..T_7 per
// input to even/odd y-Horner (y=x^2) coeffs; scatter into g_pack / g_e0h.
// grid = 128 blocks x 256 threads; block handles 16 features = 2 inputs.
// ---------------------------------------------------------------------------
__global__ void kan_prep(const float* __restrict__ coeffs) {
    // Let the dependent (main) kernel launch immediately: its pre-wait work
    // (x loads) does not touch anything prep writes.
    asm volatile("griddepcontrol.launch_dependents;");

    __shared__ float sh[16][16];
    __shared__ float cs[16];
    __shared__ float se0[2];
    const int t  = threadIdx.x;
    const int fl = t & 15;
    const int g  = t >> 4;
    const int f  = blockIdx.x * 16 + fl;

    float s = 0.0f;
#pragma unroll
    for (int n = 0; n < 8; n++)
        s += coeffs[(g * 8 + n) * NFEAT + f];
    sh[g][fl] = s;
    __syncthreads();

    if (t < 16) {
        float c = 0.0f;
#pragma unroll
        for (int gg = 0; gg < 16; gg++) c += sh[gg][t];
        cs[t] = c;
    }
    __syncthreads();

    if (t < 2) {
        const int i = blockIdx.x * 2 + t;   // global input index
        float C[8];
#pragma unroll
        for (int d = 0; d < 8; d++) C[d] = cs[t * 8 + d];

        // T0=1; T1=x; T2=2y-1; T3=x(4y-3); T4=8y^2-8y+1; T5=x(16y^2-20y+5)
        // T6=32y^3-48y^2+18y-1; T7=x(64y^3-112y^2+56y-7)   (y = x^2)
        float cf[8];
        cf[0] = C[0] - C[2] + C[4] - C[6];               // e0
        cf[1] = 2.f*C[2] - 8.f*C[4] + 18.f*C[6];         // e1
        cf[2] = 8.f*C[4] - 48.f*C[6];                    // e2
        cf[3] = 32.f*C[6];                               // e3
        cf[4] = C[1] - 3.f*C[3] + 5.f*C[5] - 7.f*C[7];   // o0
        cf[5] = 4.f*C[3] - 20.f*C[5] + 56.f*C[7];        // o1
        cf[6] = 16.f*C[5] - 112.f*C[7];                  // o2
        cf[7] = 64.f*C[7];                               // o3

        const int p    = i >> 1;       // pair index
        const int lane = p >> 2;       // owning lane
        const int q    = p & 3;        // pair-within-lane
        const int e    = i & 1;        // element within pair
#pragma unroll
        for (int j = 0; j < 8; j++) {
            const int gj = j >> 1;
            g_pack[((q * 4 + gj) * 32 + lane) * 4 + (j & 1) * 2 + e] = cf[j];
        }
        se0[t] = cf[0];
    }
    __syncthreads();
    if (t == 0) g_e0h[blockIdx.x] = se0[0] + se0[1];
}

// ---------------------------------------------------------------------------
// Main kernel (round-2 structure, proven fastest): persistent, 304 blocks x
// 8 warps, each warp grid-strides over 4-row groups with 8 LDG.128 in
// flight. PDL: the first group's x loads + L2 prefetch of the second group
// are issued BEFORE griddepcontrol.wait, overlapping prep's execution.
// e0 is folded into a per-lane additive constant (E0), saving one packed op
// per pair and shortening the accumulator chain.
// ---------------------------------------------------------------------------
__global__ __launch_bounds__(THREADS, 2)
void kan_main(const float* __restrict__ x, float* __restrict__ out) {
    const int lane   = threadIdx.x & 31;
    const int w      = threadIdx.x >> 5;
    const int warpId = blockIdx.x * (THREADS / 32) + w;

    const float4* __restrict__ xr = reinterpret_cast<const float4*>(x);

    // ---- pre-wait: start streaming x while prep still runs ----
    int grp = warpId;                     // < 2432 < NG4, always valid
    float4 xa[4], xb[4];
    {
        const int base = grp * 64 + lane * 2;   // group row-stride: 4*64 f4
        // group = 4 rows of 64 float4; base of group g is g*256
    }
    const int base0 = grp * 256 + lane * 2;
#pragma unroll
    for (int r = 0; r < 4; r++) {
        xa[r] = xr[base0 + r * 64];
        xb[r] = xr[base0 + r * 64 + 1];
    }
    // L2-prefetch the second group (no register cost).
    {
        const int g2 = grp + NWARPS;
        if (g2 < NG4) {
            const char* pf = reinterpret_cast<const char*>(xr + g2 * 256 + lane * 2);
#pragma unroll
            for (int r = 0; r < 4; r++)
                asm volatile("prefetch.global.L2 [%0];" :: "l"(pf + r * 1024));
        }
    }

    // ---- wait for prep's writes (g_pack, g_e0h) to be visible ----
    asm volatile("griddepcontrol.wait;" ::: "memory");

    // Coefficient table in registers for the warp's whole lifetime.
    const float4* __restrict__ cp = reinterpret_cast<const float4*>(g_pack);
    float4 v[16];
#pragma unroll
    for (int m = 0; m < 16; m++) v[m] = cp[m * 32 + lane];
    const float E0 = g_e0h[4 * lane] + g_e0h[4 * lane + 1]
                   + g_e0h[4 * lane + 2] + g_e0h[4 * lane + 3];

    while (true) {
#pragma unroll
        for (int r = 0; r < 4; r++) {
            float2 xp[4];
            xp[0] = make_float2(xa[r].x, xa[r].y);
            xp[1] = make_float2(xa[r].z, xa[r].w);
            xp[2] = make_float2(xb[r].x, xb[r].y);
            xp[3] = make_float2(xb[r].z, xb[r].w);

            float2 acc = make_float2(E0, 0.0f);
#pragma unroll
            for (int q = 0; q < 4; q++) {
                const float2 X = xp[q];
                const float2 Y = fmul2(X, X);
                const float4 g0 = v[q * 4 + 0];   // (e0, e1) — e0 unused here
                const float4 g1 = v[q * 4 + 1];   // (e2, e3)
                const float4 g2 = v[q * 4 + 2];   // (o0, o1)
                const float4 g3 = v[q * 4 + 3];   // (o2, o3)
                const float2 e1 = make_float2(g0.z, g0.w);
                const float2 e2 = make_float2(g1.x, g1.y), e3 = make_float2(g1.z, g1.w);
                const float2 o0 = make_float2(g2.x, g2.y), o1 = make_float2(g2.z, g2.w);
                const float2 o2 = make_float2(g3.x, g3.y), o3 = make_float2(g3.z, g3.w);

                // even (minus e0): Y * (e1 + Y*(e2 + Y*e3))
                float2 ev = ffma2(e3, Y, e2);
                ev = ffma2(ev, Y, e1);
                acc = ffma2(ev, Y, acc);
                // odd: X * (o0 + Y*(o1 + Y*(o2 + Y*o3)))
                float2 od = ffma2(o3, Y, o2);
                od = ffma2(od, Y, o1);
                od = ffma2(od, Y, o0);
                acc = ffma2(od, X, acc);
            }
            float s = acc.x + acc.y;
#pragma unroll
            for (int off = 16; off; off >>= 1)
                s += __shfl_xor_sync(0xffffffffu, s, off);
            if (lane == 0) out[grp * 4 + r] = s;
        }

        grp += NWARPS;
        if (grp >= NG4) break;

        const int base = grp * 256 + lane * 2;
#pragma unroll
        for (int r = 0; r < 4; r++) {
            xa[r] = xr[base + r * 64];
            xb[r] = xr[base + r * 64 + 1];
        }
    }
}

// ---------------------------------------------------------------------------
extern "C" void kernel_launch(void* const* d_in, const int* in_sizes, int n_in,
                              void* d_out, int out_size) {
    const float* x      = (const float*)d_in[0];   // [32768, 256]
    const float* coeffs = (const float*)d_in[1];   // [128, 2048]
    float* out          = (float*)d_out;           // [32768, 1]
    (void)in_sizes; (void)n_in; (void)out_size;

    kan_prep<<<NFEAT / 16, 256>>>(coeffs);

    // Main launched with programmatic stream serialization: it may start
    // while prep runs; griddepcontrol.wait inside orders the g_pack reads.
    cudaLaunchConfig_t cfg = {};
    cfg.gridDim  = dim3(GRID_MAIN);
    cfg.blockDim = dim3(THREADS);
    cfg.dynamicSmemBytes = 0;
    cfg.stream   = 0;   // legacy default stream (same as <<<>>>)
    cudaLaunchAttribute at[1];
    at[0].id = cudaLaunchAttributeProgrammaticStreamSerialization;
    at[0].val.programmaticStreamSerializationAllowed = 1;
    cfg.attrs   = at;
    cfg.numAttrs = 1;
    cudaLaunchKernelEx(&cfg, kan_main, x, out);
}